// round 9
// baseline (speedup 1.0000x reference)
#include <cuda_runtime.h>

// GAEChamferLoss: B=16, C=3, N=4096, mask in {0,1}.
// loss = mean_b( sum_{valid m} min_{valid n} ||x_n - y_m||^2 / cnt )
//      + mean_b( sum_{valid n} min_{valid m} ||x_n - y_m||^2 / cnt )

#define BB 16
#define NN 4096
#define BIGV 1e10f

#define INNER_SPLITS 4
#define THREADS 256
#define OUTER_PER_THREAD 4
#define OUTER_PER_BLOCK (THREADS * OUTER_PER_THREAD)            // 1024
#define OUTER_CHUNKS ((NN + OUTER_PER_BLOCK - 1) / OUTER_PER_BLOCK)  // 4
#define MAX_INNER ((NN + INNER_SPLITS - 1) / INNER_SPLITS)      // 1024

// Scratch (device globals — no allocations allowed)
__device__ float d_cx[BB * 3 * NN];   // compacted x, SoA per batch: [b][c][slot]
__device__ float d_cy[BB * 3 * NN];   // compacted y
__device__ int   d_cidx[BB * NN];     // original index per compacted slot
__device__ int   d_cnt[BB];           // valid count per batch
__device__ float d_mins[2 * BB * NN]; // [dir][b][orig_idx], init BIG
__device__ float d_sums[2 * BB];      // per (dir,b) mean of mins

__global__ void k_init() {
    int i = blockIdx.x * blockDim.x + threadIdx.x;
    if (i < 2 * BB * NN) d_mins[i] = BIGV;
    if (i < BB) d_cnt[i] = 0;
}

__global__ void k_compact(const float* __restrict__ x,
                          const float* __restrict__ y,
                          const int* __restrict__ mask) {
    int b = blockIdx.y;
    int i = blockIdx.x * blockDim.x + threadIdx.x;
    if (i >= NN) return;
    if (mask[b * NN + i]) {
        int slot = atomicAdd(&d_cnt[b], 1);
        #pragma unroll
        for (int c = 0; c < 3; c++) {
            d_cx[(b * 3 + c) * NN + slot] = x[(b * 3 + c) * NN + i];
            d_cy[(b * 3 + c) * NN + slot] = y[(b * 3 + c) * NN + i];
        }
        d_cidx[b * NN + slot] = i;
    }
}

// dir=0: outer = x (valid), inner = y (valid) -> mins2[b, orig_n]
// dir=1: outer = y (valid), inner = x (valid) -> mins1[b, orig_m]
__global__ __launch_bounds__(THREADS)
void k_main() {
    const int b = blockIdx.y;
    const int dir = blockIdx.z >> 2;                 // INNER_SPLITS = 4
    const int isplit = blockIdx.z & (INNER_SPLITS - 1);
    const int cnt = d_cnt[b];
    const int outer_base = blockIdx.x * OUTER_PER_BLOCK;
    if (outer_base >= cnt) return;

    const int chunk = (cnt + INNER_SPLITS - 1) / INNER_SPLITS;
    const int i0 = isplit * chunk;
    const int i1 = min(cnt, i0 + chunk);
    const int ilen = i1 - i0;
    if (ilen <= 0) return;

    const float* __restrict__ inner = dir ? d_cx : d_cy;
    const float* __restrict__ outer = dir ? d_cy : d_cx;

    __shared__ float s0[MAX_INNER];
    __shared__ float s1[MAX_INNER];
    __shared__ float s2[MAX_INNER];
    for (int j = threadIdx.x; j < ilen; j += THREADS) {
        s0[j] = inner[(b * 3 + 0) * NN + i0 + j];
        s1[j] = inner[(b * 3 + 1) * NN + i0 + j];
        s2[j] = inner[(b * 3 + 2) * NN + i0 + j];
    }
    __syncthreads();

    float ox[OUTER_PER_THREAD], oy[OUTER_PER_THREAD], oz[OUTER_PER_THREAD];
    float mn[OUTER_PER_THREAD];
    #pragma unroll
    for (int k = 0; k < OUTER_PER_THREAD; k++) {
        int o = outer_base + threadIdx.x + k * THREADS;
        int oc = (o < cnt) ? o : (cnt - 1);   // clamp; discarded at writeback
        ox[k] = outer[(b * 3 + 0) * NN + oc];
        oy[k] = outer[(b * 3 + 1) * NN + oc];
        oz[k] = outer[(b * 3 + 2) * NN + oc];
        mn[k] = BIGV;
    }

    #pragma unroll 2
    for (int j = 0; j < ilen; j++) {
        const float y0 = s0[j];
        const float y1 = s1[j];
        const float y2 = s2[j];
        #pragma unroll
        for (int k = 0; k < OUTER_PER_THREAD; k++) {
            float dx = ox[k] - y0;
            float dy = oy[k] - y1;
            float dz = oz[k] - y2;
            float d = fmaf(dz, dz, fmaf(dy, dy, dx * dx));  // >= 0 always
            mn[k] = fminf(mn[k], d);
        }
    }

    #pragma unroll
    for (int k = 0; k < OUTER_PER_THREAD; k++) {
        int o = outer_base + threadIdx.x + k * THREADS;
        if (o < cnt) {
            int orig = d_cidx[b * NN + o];
            // d >= 0 so int-min on the bit pattern == float-min
            atomicMin((int*)&d_mins[(dir * BB + b) * NN + orig],
                      __float_as_int(mn[k]));
        }
    }
}

__global__ void k_reduce(const int* __restrict__ mask) {
    const int b = blockIdx.x & (BB - 1);
    const int dir = blockIdx.x >> 4;
    __shared__ float red[256];
    float s = 0.f;
    for (int i = threadIdx.x; i < NN; i += 256)
        if (mask[b * NN + i]) s += d_mins[(dir * BB + b) * NN + i];
    red[threadIdx.x] = s;
    __syncthreads();
    for (int st = 128; st > 0; st >>= 1) {
        if (threadIdx.x < st) red[threadIdx.x] += red[threadIdx.x + st];
        __syncthreads();
    }
    if (threadIdx.x == 0)
        d_sums[blockIdx.x] = red[0] / (float)d_cnt[b];
}

__global__ void k_final(float* __restrict__ out) {
    if (threadIdx.x == 0) {
        float s = 0.f;
        #pragma unroll
        for (int i = 0; i < 2 * BB; i++) s += d_sums[i];
        out[0] = s / (float)BB;
    }
}

extern "C" void kernel_launch(void* const* d_in, const int* in_sizes, int n_in,
                              void* d_out, int out_size) {
    const float* x    = (const float*)d_in[0];
    const float* y    = (const float*)d_in[1];
    const int*   mask = (const int*)d_in[2];
    float* out = (float*)d_out;

    k_init<<<(2 * BB * NN + 255) / 256, 256>>>();

    dim3 gc((NN + 255) / 256, BB);
    k_compact<<<gc, 256>>>(x, y, mask);

    dim3 gm(OUTER_CHUNKS, BB, 2 * INNER_SPLITS);
    k_main<<<gm, THREADS>>>();

    k_reduce<<<2 * BB, 256>>>(mask);
    k_final<<<1, 32>>>(out);
}

// round 10
// speedup vs baseline: 1.2781x; 1.2781x over previous
#include <cuda_runtime.h>

// GAEChamferLoss: B=16, C=3, N=4096, mask in {0,1}.
// loss = mean_b( sum_{valid m} min_{valid n} ||x_n - y_m||^2 / cnt )
//      + mean_b( sum_{valid n} min_{valid m} ||x_n - y_m||^2 / cnt )
// Compaction-first; distances via d = |x|^2 + |y|^2 - 2 x.y (matches reference).

#define BB 16
#define NN 4096
#define BIGV 1e10f

#define INNER_SPLITS 8
#define THREADS 256
#define OPT 4
#define OUTER_PER_BLOCK (THREADS * OPT)                 // 1024
#define OUTER_CHUNKS ((NN + OUTER_PER_BLOCK - 1) / OUTER_PER_BLOCK)  // 4
#define MAX_INNER (NN / INNER_SPLITS)                   // 512

// Scratch (device globals — no allocations allowed)
__device__ float d_cx[BB * 3 * NN];   // compacted x, SoA per batch
__device__ float d_cy[BB * 3 * NN];   // compacted y
__device__ float d_nx[BB * NN];       // |x|^2 per compacted slot
__device__ float d_ny[BB * NN];       // |y|^2 per compacted slot
__device__ int   d_cnt[BB];
__device__ float d_mins[2 * BB * NN]; // [dir*BB+b][slot], init BIG
__device__ float d_sums[2 * BB];
__device__ int   d_done;              // static-init 0; reset by last reduce block

__global__ void k_init() {
    int t = threadIdx.x;
    if (t < 2 * BB) d_sums[t] = 0.f;
    if (t < BB) d_cnt[t] = 0;
}

__global__ void k_compact(const float* __restrict__ x,
                          const float* __restrict__ y,
                          const int* __restrict__ mask) {
    const int b = blockIdx.y;
    const int i = blockIdx.x * blockDim.x + threadIdx.x;

    // init mins for both directions (slot-indexed; all NN to be safe)
    d_mins[b * NN + i] = BIGV;
    d_mins[(BB + b) * NN + i] = BIGV;

    const int lane = threadIdx.x & 31;
    const bool valid = mask[b * NN + i] != 0;
    const unsigned bal = __ballot_sync(0xffffffffu, valid);
    int base = 0;
    if (lane == 0 && bal) base = atomicAdd(&d_cnt[b], __popc(bal));
    base = __shfl_sync(0xffffffffu, base, 0);
    if (valid) {
        const int slot = base + __popc(bal & ((1u << lane) - 1u));
        float x0 = x[(b * 3 + 0) * NN + i];
        float x1 = x[(b * 3 + 1) * NN + i];
        float x2 = x[(b * 3 + 2) * NN + i];
        float y0 = y[(b * 3 + 0) * NN + i];
        float y1 = y[(b * 3 + 1) * NN + i];
        float y2 = y[(b * 3 + 2) * NN + i];
        d_cx[(b * 3 + 0) * NN + slot] = x0;
        d_cx[(b * 3 + 1) * NN + slot] = x1;
        d_cx[(b * 3 + 2) * NN + slot] = x2;
        d_cy[(b * 3 + 0) * NN + slot] = y0;
        d_cy[(b * 3 + 1) * NN + slot] = y1;
        d_cy[(b * 3 + 2) * NN + slot] = y2;
        d_nx[b * NN + slot] = fmaf(x2, x2, fmaf(x1, x1, x0 * x0));
        d_ny[b * NN + slot] = fmaf(y2, y2, fmaf(y1, y1, y0 * y0));
    }
}

// dir=0: outer = x, inner = y; dir=1: outer = y, inner = x
__global__ __launch_bounds__(THREADS)
void k_main() {
    const int b = blockIdx.y;
    const int dir = blockIdx.z >> 3;                 // INNER_SPLITS = 8
    const int isplit = blockIdx.z & (INNER_SPLITS - 1);
    const int cnt = d_cnt[b];
    const int outer_base = blockIdx.x * OUTER_PER_BLOCK;
    if (outer_base >= cnt) return;

    const int chunk = (cnt + INNER_SPLITS - 1) / INNER_SPLITS;
    const int i0 = isplit * chunk;
    const int ilen = min(cnt, i0 + chunk) - i0;
    if (ilen <= 0) return;

    const float* __restrict__ inner  = dir ? d_cx : d_cy;
    const float* __restrict__ innern = dir ? d_nx : d_ny;
    const float* __restrict__ outer  = dir ? d_cy : d_cx;
    const float* __restrict__ outern = dir ? d_ny : d_nx;

    __shared__ float4 sIn[MAX_INNER];
    for (int j = threadIdx.x; j < ilen; j += THREADS) {
        float a = inner[(b * 3 + 0) * NN + i0 + j];
        float c = inner[(b * 3 + 1) * NN + i0 + j];
        float e = inner[(b * 3 + 2) * NN + i0 + j];
        float n = innern[b * NN + i0 + j];
        sIn[j] = make_float4(-2.f * a, -2.f * c, -2.f * e, n);
    }
    __syncthreads();

    float ox[OPT], oy[OPT], oz[OPT], xx[OPT], mn[OPT];
    #pragma unroll
    for (int k = 0; k < OPT; k++) {
        int o = outer_base + threadIdx.x + k * THREADS;
        int oc = (o < cnt) ? o : (cnt - 1);          // clamp; discarded at writeback
        ox[k] = outer[(b * 3 + 0) * NN + oc];
        oy[k] = outer[(b * 3 + 1) * NN + oc];
        oz[k] = outer[(b * 3 + 2) * NN + oc];
        xx[k] = outern[b * NN + oc];
        mn[k] = BIGV;
    }

    #pragma unroll 2
    for (int j = 0; j < ilen; j++) {
        const float4 t = sIn[j];                     // one LDS.128 broadcast
        #pragma unroll
        for (int k = 0; k < OPT; k++) {
            float d = xx[k] + t.w;                   // |x|^2 + |y|^2
            d = fmaf(t.x, ox[k], d);                 // - 2 x.y
            d = fmaf(t.y, oy[k], d);
            d = fmaf(t.z, oz[k], d);
            mn[k] = fminf(mn[k], d);
        }
    }

    #pragma unroll
    for (int k = 0; k < OPT; k++) {
        int o = outer_base + threadIdx.x + k * THREADS;
        if (o < cnt) {
            // clamp to >= 0 so int-min on bit pattern == float-min
            atomicMin((int*)&d_mins[(dir * BB + b) * NN + o],
                      __float_as_int(fmaxf(mn[k], 0.f)));
        }
    }
}

// grid (4, 32): blockIdx.y = dir*16+b, blockIdx.x = 1024-element chunk.
// Last block to finish combines everything and writes the scalar output.
__global__ void k_reduce(float* __restrict__ out) {
    const int db = blockIdx.y;          // dir*BB + b
    const int b = db & (BB - 1);
    const int cnt = d_cnt[b];
    const int base = blockIdx.x * 1024 + threadIdx.x * 4;

    float4 v = *reinterpret_cast<const float4*>(&d_mins[db * NN + base]);
    float s = 0.f;
    s += (base + 0 < cnt) ? v.x : 0.f;
    s += (base + 1 < cnt) ? v.y : 0.f;
    s += (base + 2 < cnt) ? v.z : 0.f;
    s += (base + 3 < cnt) ? v.w : 0.f;

    #pragma unroll
    for (int off = 16; off; off >>= 1) s += __shfl_xor_sync(0xffffffffu, s, off);

    __shared__ float w[8];
    if ((threadIdx.x & 31) == 0) w[threadIdx.x >> 5] = s;
    __syncthreads();

    if (threadIdx.x == 0) {
        float bs = 0.f;
        #pragma unroll
        for (int i = 0; i < 8; i++) bs += w[i];
        atomicAdd(&d_sums[db], bs);
        __threadfence();
        int t = atomicAdd(&d_done, 1);
        if (t == 4 * 2 * BB - 1) {       // last block: finalize
            float tot = 0.f;
            #pragma unroll
            for (int i = 0; i < 2 * BB; i++) {
                float sv = *((volatile float*)&d_sums[i]);
                tot += sv / (float)d_cnt[i & (BB - 1)];
            }
            out[0] = tot / (float)BB;
            d_done = 0;                  // reset for next replay
        }
    }
}

extern "C" void kernel_launch(void* const* d_in, const int* in_sizes, int n_in,
                              void* d_out, int out_size) {
    const float* x    = (const float*)d_in[0];
    const float* y    = (const float*)d_in[1];
    const int*   mask = (const int*)d_in[2];
    float* out = (float*)d_out;

    k_init<<<1, 64>>>();

    dim3 gc(NN / 256, BB);
    k_compact<<<gc, 256>>>(x, y, mask);

    dim3 gm(OUTER_CHUNKS, BB, 2 * INNER_SPLITS);
    k_main<<<gm, THREADS>>>();

    dim3 gr(NN / 1024, 2 * BB);
    k_reduce<<<gr, 256>>>(out);
}

// round 11
// speedup vs baseline: 1.7449x; 1.3652x over previous
#include <cuda_runtime.h>

// GAEChamferLoss: B=16, C=3, N=4096, mask in {0,1}. Single fused persistent
// kernel: init -> compact -> pairwise-min -> reduce -> finalize, separated by
// software grid barriers (256 co-resident blocks).
// d = |x|^2 + |y|^2 - 2 x.y, with |y|^2 folded into the FMA chain and |x|^2
// added after the min (min distributes over the per-outer constant).

#define BB 16
#define NN 4096
#define BIGV 1e10f

#define NBLK 256
#define NTHR 256
#define IS 4                       // inner splits
#define OC 4                       // outer chunks of 1024
#define OPT 4                      // outers per thread
#define OUTER_PER_BLOCK (NTHR * OPT)   // 1024
#define MAX_INNER (NN / IS)            // 1024 worst case

// Scratch (device globals — no allocations allowed)
__device__ float d_cx[BB * 3 * NN];
__device__ float d_cy[BB * 3 * NN];
__device__ float d_nx[BB * NN];
__device__ float d_ny[BB * NN];
__device__ int   d_cnt[BB];
__device__ __align__(16) float d_mins[2 * BB * NN];
__device__ float d_sums[2 * BB];
__device__ unsigned d_bar_arrive;          // static 0
__device__ volatile unsigned d_bar_gen;    // monotonically increasing

__device__ __forceinline__ void grid_barrier() {
    __syncthreads();
    __threadfence();
    if (threadIdx.x == 0) {
        unsigned gen = d_bar_gen;
        if (atomicAdd(&d_bar_arrive, 1u) == NBLK - 1) {
            atomicExch(&d_bar_arrive, 0u);
            __threadfence();
            d_bar_gen = gen + 1;
        } else {
            while (d_bar_gen == gen) { }
        }
    }
    __syncthreads();
}

__global__ __launch_bounds__(NTHR, 2)
void k_fused(const float* __restrict__ x, const float* __restrict__ y,
             const int* __restrict__ mask, float* __restrict__ out)
{
    const int tid = threadIdx.x;
    const int bid = blockIdx.x;
    __shared__ float4 sIn[MAX_INNER];
    __shared__ float sRed[NTHR / 32];

    // ---------- Phase 0: init (all cross-phase stores via .cg = L2 only) ----
    if (bid == 0) {
        if (tid < 2 * BB) __stcg(&d_sums[tid], 0.f);
        if (tid < BB) __stcg(&d_cnt[tid], 0);
    }
    {
        int base = bid * (2 * BB * NN / NBLK) + tid * 2;   // 512 floats/block
        __stcg((float2*)&d_mins[base], make_float2(BIGV, BIGV));
    }
    grid_barrier();

    // ---------- Phase 1: warp-aggregated compaction + norms ----------------
    {
        const int g = bid * NTHR + tid;        // 0..65535 = [b][i]
        const int b = g >> 12;
        const int i = g & (NN - 1);
        const int lane = tid & 31;
        const bool valid = mask[g] != 0;
        const unsigned bal = __ballot_sync(0xffffffffu, valid);
        int base = 0;
        if (lane == 0 && bal) base = atomicAdd(&d_cnt[b], __popc(bal));
        base = __shfl_sync(0xffffffffu, base, 0);
        if (valid) {
            const int slot = base + __popc(bal & ((1u << lane) - 1u));
            float x0 = x[(b * 3 + 0) * NN + i];
            float x1 = x[(b * 3 + 1) * NN + i];
            float x2 = x[(b * 3 + 2) * NN + i];
            float y0 = y[(b * 3 + 0) * NN + i];
            float y1 = y[(b * 3 + 1) * NN + i];
            float y2 = y[(b * 3 + 2) * NN + i];
            __stcg(&d_cx[(b * 3 + 0) * NN + slot], x0);
            __stcg(&d_cx[(b * 3 + 1) * NN + slot], x1);
            __stcg(&d_cx[(b * 3 + 2) * NN + slot], x2);
            __stcg(&d_cy[(b * 3 + 0) * NN + slot], y0);
            __stcg(&d_cy[(b * 3 + 1) * NN + slot], y1);
            __stcg(&d_cy[(b * 3 + 2) * NN + slot], y2);
            __stcg(&d_nx[b * NN + slot], fmaf(x2, x2, fmaf(x1, x1, x0 * x0)));
            __stcg(&d_ny[b * NN + slot], fmaf(y2, y2, fmaf(y1, y1, y0 * y0)));
        }
    }
    grid_barrier();

    // ---------- Phase 2: pairwise mins. 512 units, oc-major for balance ----
    // unit u: oc = u>>7, dir = (u>>6)&1, isplit = (u>>4)&3, b = u&15
    for (int u = bid; u < OC * 2 * IS * BB; u += NBLK) {
        const int oc = u >> 7;
        const int dir = (u >> 6) & 1;
        const int isplit = (u >> 4) & 3;
        const int b = u & 15;
        const int cnt = d_cnt[b];
        const int outer_base = oc * OUTER_PER_BLOCK;
        if (outer_base >= cnt) continue;

        const int chunk = (cnt + IS - 1) / IS;
        const int i0 = isplit * chunk;
        const int ilen = min(cnt, i0 + chunk) - i0;
        if (ilen <= 0) continue;

        const float* __restrict__ inner  = dir ? d_cx : d_cy;
        const float* __restrict__ innern = dir ? d_nx : d_ny;
        const float* __restrict__ outer  = dir ? d_cy : d_cx;
        const float* __restrict__ outern = dir ? d_ny : d_nx;

        __syncthreads();                       // protect sIn reuse
        for (int j = tid; j < ilen; j += NTHR) {
            float a = inner[(b * 3 + 0) * NN + i0 + j];
            float c = inner[(b * 3 + 1) * NN + i0 + j];
            float e = inner[(b * 3 + 2) * NN + i0 + j];
            float n = innern[b * NN + i0 + j];
            sIn[j] = make_float4(-2.f * a, -2.f * c, -2.f * e, n);
        }
        __syncthreads();

        float ox[OPT], oy[OPT], oz[OPT], xx[OPT], mn[OPT];
        #pragma unroll
        for (int k = 0; k < OPT; k++) {
            int o = outer_base + tid + k * NTHR;
            int ocl = (o < cnt) ? o : (cnt - 1);   // clamp; dropped at writeback
            ox[k] = outer[(b * 3 + 0) * NN + ocl];
            oy[k] = outer[(b * 3 + 1) * NN + ocl];
            oz[k] = outer[(b * 3 + 2) * NN + ocl];
            xx[k] = outern[b * NN + ocl];
            mn[k] = BIGV;
        }

        #pragma unroll 2
        for (int j = 0; j < ilen; j++) {
            const float4 t = sIn[j];               // one LDS.128 broadcast
            #pragma unroll
            for (int k = 0; k < OPT; k++) {
                float d = fmaf(t.x, ox[k], t.w);   // |y|^2 - 2 x.y
                d = fmaf(t.y, oy[k], d);
                d = fmaf(t.z, oz[k], d);
                mn[k] = fminf(mn[k], d);           // 4 instr/pair
            }
        }

        #pragma unroll
        for (int k = 0; k < OPT; k++) {
            int o = outer_base + tid + k * NTHR;
            if (o < cnt) {
                float v = fmaxf(mn[k] + xx[k], 0.f);   // >=0 so int-min == fp-min
                atomicMin((int*)&d_mins[(dir * BB + b) * NN + o],
                          __float_as_int(v));
            }
        }
    }
    grid_barrier();

    // ---------- Phase 3: per-(dir,b) masked sums. 256 units = NBLK ---------
    {
        const int db = bid >> 3;                 // dir*BB + b
        const int b = db & (BB - 1);
        const int chunk = bid & 7;
        const int cnt = d_cnt[b];
        const int base = chunk * 512 + tid * 2;

        float2 v = *reinterpret_cast<const float2*>(&d_mins[db * NN + base]);
        float s = ((base < cnt) ? v.x : 0.f) + ((base + 1 < cnt) ? v.y : 0.f);
        #pragma unroll
        for (int off = 16; off; off >>= 1)
            s += __shfl_xor_sync(0xffffffffu, s, off);
        if ((tid & 31) == 0) sRed[tid >> 5] = s;
        __syncthreads();
        if (tid == 0) {
            float bs = 0.f;
            #pragma unroll
            for (int i = 0; i < NTHR / 32; i++) bs += sRed[i];
            atomicAdd(&d_sums[db], bs);
        }
    }
    grid_barrier();

    // ---------- Phase 4: parallel finalize ---------------------------------
    if (bid == 0 && tid < 32) {
        float v = __ldcg(&d_sums[tid]) / (float)__ldcg(&d_cnt[tid & (BB - 1)]);
        #pragma unroll
        for (int off = 16; off; off >>= 1)
            v += __shfl_xor_sync(0xffffffffu, v, off);
        if (tid == 0) out[0] = v / (float)BB;
    }
}

extern "C" void kernel_launch(void* const* d_in, const int* in_sizes, int n_in,
                              void* d_out, int out_size) {
    const float* x    = (const float*)d_in[0];
    const float* y    = (const float*)d_in[1];
    const int*   mask = (const int*)d_in[2];
    float* out = (float*)d_out;

    k_fused<<<NBLK, NTHR>>>(x, y, mask, out);
}

// round 12
// speedup vs baseline: 1.9329x; 1.1078x over previous
#include <cuda_runtime.h>

// GAEChamferLoss: B=16, C=3, N=4096, mask in {0,1}. Single fused persistent
// kernel: init -> compact -> pairwise-min -> reduce -> finalize, separated by
// software grid barriers (256 co-resident blocks).
// d = |x|^2 + |y|^2 - 2 x.y; |y|^2 folded into the FMA chain, |x|^2 added
// after the min. Hot loop uses packed fma.rn.f32x2 (2 outers per instruction)
// with the inner tile pre-duplicated in smem so broadcasts need no pack movs.

#define BB 16
#define NN 4096
#define BIGV 1e10f

#define NBLK 256
#define NTHR 256
#define IS 4                       // inner splits
#define OC 4                       // outer chunks of 1024
#define OPT 4                      // outers per thread (2 packed pairs)
#define OUTER_PER_BLOCK (NTHR * OPT)   // 1024
#define MAX_INNER (NN / IS)            // 1024 worst case

typedef unsigned long long u64;

__device__ __forceinline__ u64 pack2(float lo, float hi) {
    u64 r; asm("mov.b64 %0, {%1, %2};" : "=l"(r) : "f"(lo), "f"(hi)); return r;
}
__device__ __forceinline__ u64 fma2(u64 a, u64 b, u64 c) {
    u64 d;
    asm("fma.rn.f32x2 %0, %1, %2, %3;" : "=l"(d) : "l"(a), "l"(b), "l"(c));
    return d;
}
__device__ __forceinline__ void unpack2(u64 v, float& lo, float& hi) {
    asm("mov.b64 {%0, %1}, %2;" : "=f"(lo), "=f"(hi) : "l"(v));
}

// Scratch (device globals — no allocations allowed)
__device__ float d_cx[BB * 3 * NN];
__device__ float d_cy[BB * 3 * NN];
__device__ float d_nx[BB * NN];
__device__ float d_ny[BB * NN];
__device__ int   d_cnt[BB];
__device__ __align__(16) float d_mins[2 * BB * NN];
__device__ float d_sums[2 * BB];
__device__ unsigned d_bar_arrive;          // static 0
__device__ volatile unsigned d_bar_gen;    // monotonically increasing

__device__ __forceinline__ void grid_barrier() {
    __syncthreads();
    __threadfence();
    if (threadIdx.x == 0) {
        unsigned gen = d_bar_gen;
        if (atomicAdd(&d_bar_arrive, 1u) == NBLK - 1) {
            atomicExch(&d_bar_arrive, 0u);
            __threadfence();
            d_bar_gen = gen + 1;
        } else {
            while (d_bar_gen == gen) { }
        }
    }
    __syncthreads();
}

__global__ __launch_bounds__(NTHR, 2)
void k_fused(const float* __restrict__ x, const float* __restrict__ y,
             const int* __restrict__ mask, float* __restrict__ out)
{
    const int tid = threadIdx.x;
    const int bid = blockIdx.x;
    // per inner point: two float4s = {-2a,-2a,-2c,-2c} and {-2e,-2e, n, n}
    __shared__ float4 sIn[2 * MAX_INNER];          // 32 KB
    __shared__ float sRed[NTHR / 32];

    // ---------- Phase 0: init (cross-phase stores via .cg = L2 only) -------
    if (bid == 0) {
        if (tid < 2 * BB) __stcg(&d_sums[tid], 0.f);
        if (tid < BB) __stcg(&d_cnt[tid], 0);
    }
    {
        int base = bid * (2 * BB * NN / NBLK) + tid * 2;   // 512 floats/block
        __stcg((float2*)&d_mins[base], make_float2(BIGV, BIGV));
    }
    grid_barrier();

    // ---------- Phase 1: warp-aggregated compaction + norms ----------------
    {
        const int g = bid * NTHR + tid;        // 0..65535 = [b][i]
        const int b = g >> 12;
        const int i = g & (NN - 1);
        const int lane = tid & 31;
        const bool valid = mask[g] != 0;
        const unsigned bal = __ballot_sync(0xffffffffu, valid);
        int base = 0;
        if (lane == 0 && bal) base = atomicAdd(&d_cnt[b], __popc(bal));
        base = __shfl_sync(0xffffffffu, base, 0);
        if (valid) {
            const int slot = base + __popc(bal & ((1u << lane) - 1u));
            float x0 = x[(b * 3 + 0) * NN + i];
            float x1 = x[(b * 3 + 1) * NN + i];
            float x2 = x[(b * 3 + 2) * NN + i];
            float y0 = y[(b * 3 + 0) * NN + i];
            float y1 = y[(b * 3 + 1) * NN + i];
            float y2 = y[(b * 3 + 2) * NN + i];
            __stcg(&d_cx[(b * 3 + 0) * NN + slot], x0);
            __stcg(&d_cx[(b * 3 + 1) * NN + slot], x1);
            __stcg(&d_cx[(b * 3 + 2) * NN + slot], x2);
            __stcg(&d_cy[(b * 3 + 0) * NN + slot], y0);
            __stcg(&d_cy[(b * 3 + 1) * NN + slot], y1);
            __stcg(&d_cy[(b * 3 + 2) * NN + slot], y2);
            __stcg(&d_nx[b * NN + slot], fmaf(x2, x2, fmaf(x1, x1, x0 * x0)));
            __stcg(&d_ny[b * NN + slot], fmaf(y2, y2, fmaf(y1, y1, y0 * y0)));
        }
    }
    grid_barrier();

    // ---------- Phase 2: pairwise mins. 512 units, oc-major for balance ----
    // unit u: oc = u>>7, dir = (u>>6)&1, isplit = (u>>4)&3, b = u&15
    const unsigned sbase = (unsigned)__cvta_generic_to_shared(sIn);
    for (int u = bid; u < OC * 2 * IS * BB; u += NBLK) {
        const int oc = u >> 7;
        const int dir = (u >> 6) & 1;
        const int isplit = (u >> 4) & 3;
        const int b = u & 15;
        const int cnt = d_cnt[b];
        const int outer_base = oc * OUTER_PER_BLOCK;
        if (outer_base >= cnt) continue;

        const int chunk = (cnt + IS - 1) / IS;
        const int i0 = isplit * chunk;
        const int ilen = min(cnt, i0 + chunk) - i0;
        if (ilen <= 0) continue;

        const float* __restrict__ inner  = dir ? d_cx : d_cy;
        const float* __restrict__ innern = dir ? d_nx : d_ny;
        const float* __restrict__ outer  = dir ? d_cy : d_cx;
        const float* __restrict__ outern = dir ? d_ny : d_nx;

        __syncthreads();                       // protect sIn reuse
        for (int j = tid; j < ilen; j += NTHR) {
            float a = -2.f * inner[(b * 3 + 0) * NN + i0 + j];
            float c = -2.f * inner[(b * 3 + 1) * NN + i0 + j];
            float e = -2.f * inner[(b * 3 + 2) * NN + i0 + j];
            float n = innern[b * NN + i0 + j];
            sIn[2 * j]     = make_float4(a, a, c, c);
            sIn[2 * j + 1] = make_float4(e, e, n, n);
        }
        __syncthreads();

        // pack the 4 outers into 2 f32x2 pairs
        u64 ox2[2], oy2[2], oz2[2];
        float xx[OPT], mn[OPT];
        #pragma unroll
        for (int p = 0; p < 2; p++) {
            int o0 = outer_base + tid + (2 * p) * NTHR;
            int o1 = o0 + NTHR;
            int c0 = (o0 < cnt) ? o0 : (cnt - 1);   // clamp; dropped at writeback
            int c1 = (o1 < cnt) ? o1 : (cnt - 1);
            ox2[p] = pack2(outer[(b * 3 + 0) * NN + c0], outer[(b * 3 + 0) * NN + c1]);
            oy2[p] = pack2(outer[(b * 3 + 1) * NN + c0], outer[(b * 3 + 1) * NN + c1]);
            oz2[p] = pack2(outer[(b * 3 + 2) * NN + c0], outer[(b * 3 + 2) * NN + c1]);
            xx[2 * p]     = outern[b * NN + c0];
            xx[2 * p + 1] = outern[b * NN + c1];
            mn[2 * p] = BIGV; mn[2 * p + 1] = BIGV;
        }

        #pragma unroll 4
        for (int j = 0; j < ilen; j++) {
            u64 ta, tc, te, tn;
            unsigned addr = sbase + (unsigned)j * 32u;
            asm volatile("ld.shared.v2.u64 {%0, %1}, [%2];"
                         : "=l"(ta), "=l"(tc) : "r"(addr));
            asm volatile("ld.shared.v2.u64 {%0, %1}, [%2];"
                         : "=l"(te), "=l"(tn) : "r"(addr + 16u));
            #pragma unroll
            for (int p = 0; p < 2; p++) {
                u64 d = fma2(ta, ox2[p], tn);      // |y|^2 - 2x.y (packed x2)
                d = fma2(tc, oy2[p], d);
                d = fma2(te, oz2[p], d);
                float lo, hi;
                unpack2(d, lo, hi);                 // register-pair rename
                mn[2 * p]     = fminf(mn[2 * p], lo);
                mn[2 * p + 1] = fminf(mn[2 * p + 1], hi);
            }
        }

        #pragma unroll
        for (int k = 0; k < OPT; k++) {
            int o = outer_base + tid + k * NTHR;
            if (o < cnt) {
                float v = fmaxf(mn[k] + xx[k], 0.f);   // >=0 so int-min == fp-min
                atomicMin((int*)&d_mins[(dir * BB + b) * NN + o],
                          __float_as_int(v));
            }
        }
    }
    grid_barrier();

    // ---------- Phase 3: per-(dir,b) masked sums. 256 units = NBLK ---------
    {
        const int db = bid >> 3;                 // dir*BB + b
        const int b = db & (BB - 1);
        const int chunk = bid & 7;
        const int cnt = d_cnt[b];
        const int base = chunk * 512 + tid * 2;

        float2 v = *reinterpret_cast<const float2*>(&d_mins[db * NN + base]);
        float s = ((base < cnt) ? v.x : 0.f) + ((base + 1 < cnt) ? v.y : 0.f);
        #pragma unroll
        for (int off = 16; off; off >>= 1)
            s += __shfl_xor_sync(0xffffffffu, s, off);
        if ((tid & 31) == 0) sRed[tid >> 5] = s;
        __syncthreads();
        if (tid == 0) {
            float bs = 0.f;
            #pragma unroll
            for (int i = 0; i < NTHR / 32; i++) bs += sRed[i];
            atomicAdd(&d_sums[db], bs);
        }
    }
    grid_barrier();

    // ---------- Phase 4: parallel finalize ---------------------------------
    if (bid == 0 && tid < 32) {
        float v = __ldcg(&d_sums[tid]) / (float)__ldcg(&d_cnt[tid & (BB - 1)]);
        #pragma unroll
        for (int off = 16; off; off >>= 1)
            v += __shfl_xor_sync(0xffffffffu, v, off);
        if (tid == 0) out[0] = v / (float)BB;
    }
}

extern "C" void kernel_launch(void* const* d_in, const int* in_sizes, int n_in,
                              void* d_out, int out_size) {
    const float* x    = (const float*)d_in[0];
    const float* y    = (const float*)d_in[1];
    const int*   mask = (const int*)d_in[2];
    float* out = (float*)d_out;

    k_fused<<<NBLK, NTHR>>>(x, y, mask, out);
}

// round 13
// speedup vs baseline: 2.1095x; 1.0914x over previous
#include <cuda_runtime.h>

// GAEChamferLoss: B=16, C=3, N=4096, mask in {0,1}. Single fused persistent
// kernel: init -> compact -> pairwise-min -> reduce -> finalize, separated by
// software grid barriers (444 co-resident blocks, 3 per SM).
// d = |x|^2 + |y|^2 - 2 x.y; |y|^2 folded into the FMA chain, |x|^2 added
// after the min. Hot loop uses packed fma.rn.f32x2 (2 outers/instruction) with
// the inner tile pre-duplicated in smem so broadcasts need no pack movs.
// Phase 2 is a work-stealing queue over 1024 units for perfect balance.

#define BB 16
#define NN 4096
#define BIGV 1e10f

#define NBLK 444                   // 3 x 148 (<= 3 x 152 on GB300)
#define NTHR 256
#define IS 8                       // inner splits
#define OC 4                       // outer chunks of 1024 (covers cnt<=4096)
#define OPT 4                      // outers per thread (2 packed pairs)
#define OUTER_PER_BLOCK (NTHR * OPT)   // 1024
#define MAX_INNER (NN / IS)            // 512 worst case
#define NUNITS (OC * 2 * IS * BB)      // 1024

typedef unsigned long long u64;

__device__ __forceinline__ u64 pack2(float lo, float hi) {
    u64 r; asm("mov.b64 %0, {%1, %2};" : "=l"(r) : "f"(lo), "f"(hi)); return r;
}
__device__ __forceinline__ u64 fma2(u64 a, u64 b, u64 c) {
    u64 d;
    asm("fma.rn.f32x2 %0, %1, %2, %3;" : "=l"(d) : "l"(a), "l"(b), "l"(c));
    return d;
}
__device__ __forceinline__ void unpack2(u64 v, float& lo, float& hi) {
    asm("mov.b64 {%0, %1}, %2;" : "=f"(lo), "=f"(hi) : "l"(v));
}

// Scratch (device globals — no allocations allowed)
__device__ float d_cx[BB * 3 * NN];
__device__ float d_cy[BB * 3 * NN];
__device__ float d_nx[BB * NN];
__device__ float d_ny[BB * NN];
__device__ int   d_cnt[BB];
__device__ __align__(16) float d_mins[2 * BB * NN];
__device__ float d_sums[2 * BB];
__device__ int   d_unit;                   // work-steal cursor
__device__ unsigned d_bar_arrive;          // static 0
__device__ volatile unsigned d_bar_gen;    // monotonically increasing

__device__ __forceinline__ void grid_barrier() {
    __syncthreads();
    __threadfence();
    if (threadIdx.x == 0) {
        unsigned gen = d_bar_gen;
        if (atomicAdd(&d_bar_arrive, 1u) == NBLK - 1) {
            atomicExch(&d_bar_arrive, 0u);
            __threadfence();
            d_bar_gen = gen + 1;
        } else {
            while (d_bar_gen == gen) { }
        }
    }
    __syncthreads();
}

__global__ __launch_bounds__(NTHR, 3)
void k_fused(const float* __restrict__ x, const float* __restrict__ y,
             const int* __restrict__ mask, float* __restrict__ out)
{
    const int tid = threadIdx.x;
    const int bid = blockIdx.x;
    // per inner point: two float4s = {-2a,-2a,-2c,-2c} and {-2e,-2e, n, n}
    __shared__ float4 sIn[2 * MAX_INNER];          // 16 KB
    __shared__ float sRed[NTHR / 32];
    __shared__ int sU;

    // ---------- Phase 0: init (cross-phase stores via .cg = L2 only) -------
    if (bid == 0) {
        if (tid < 2 * BB) __stcg(&d_sums[tid], 0.f);
        if (tid < BB) __stcg(&d_cnt[tid], 0);
        if (tid == 0) __stcg(&d_unit, 0);
    }
    {
        int idx = bid * NTHR + tid;                 // float2 slots: 65536 total
        if (idx < BB * NN)
            __stcg((float2*)&d_mins[idx * 2], make_float2(BIGV, BIGV));
    }
    grid_barrier();

    // ---------- Phase 1: warp-aggregated compaction + norms ----------------
    {
        const int g = bid * NTHR + tid;             // [b][i], 65536 total
        if (g < BB * NN) {
            const int b = g >> 12;
            const int i = g & (NN - 1);
            const int lane = tid & 31;
            const bool valid = mask[g] != 0;
            const unsigned bal = __ballot_sync(0xffffffffu, valid);
            int base = 0;
            if (lane == 0 && bal) base = atomicAdd(&d_cnt[b], __popc(bal));
            base = __shfl_sync(0xffffffffu, base, 0);
            if (valid) {
                const int slot = base + __popc(bal & ((1u << lane) - 1u));
                float x0 = x[(b * 3 + 0) * NN + i];
                float x1 = x[(b * 3 + 1) * NN + i];
                float x2 = x[(b * 3 + 2) * NN + i];
                float y0 = y[(b * 3 + 0) * NN + i];
                float y1 = y[(b * 3 + 1) * NN + i];
                float y2 = y[(b * 3 + 2) * NN + i];
                __stcg(&d_cx[(b * 3 + 0) * NN + slot], x0);
                __stcg(&d_cx[(b * 3 + 1) * NN + slot], x1);
                __stcg(&d_cx[(b * 3 + 2) * NN + slot], x2);
                __stcg(&d_cy[(b * 3 + 0) * NN + slot], y0);
                __stcg(&d_cy[(b * 3 + 1) * NN + slot], y1);
                __stcg(&d_cy[(b * 3 + 2) * NN + slot], y2);
                __stcg(&d_nx[b * NN + slot], fmaf(x2, x2, fmaf(x1, x1, x0 * x0)));
                __stcg(&d_ny[b * NN + slot], fmaf(y2, y2, fmaf(y1, y1, y0 * y0)));
            }
        }
    }
    grid_barrier();

    // ---------- Phase 2: pairwise mins, work-stealing over 1024 units ------
    // unit u (oc-major => heavy units pulled first):
    //   b = u&15, isplit = (u>>4)&7, dir = (u>>7)&1, oc = u>>8
    const unsigned sbase = (unsigned)__cvta_generic_to_shared(sIn);
    for (;;) {
        __syncthreads();                   // protects sIn reuse + sU
        if (tid == 0) sU = atomicAdd(&d_unit, 1);
        __syncthreads();
        const int u = sU;
        if (u >= NUNITS) break;

        const int b = u & 15;
        const int isplit = (u >> 4) & 7;
        const int dir = (u >> 7) & 1;
        const int oc = u >> 8;
        const int cnt = d_cnt[b];
        const int outer_base = oc * OUTER_PER_BLOCK;
        if (outer_base >= cnt) continue;

        const int chunk = (cnt + IS - 1) / IS;
        const int i0 = isplit * chunk;
        const int ilen = min(cnt, i0 + chunk) - i0;
        if (ilen <= 0) continue;

        const float* __restrict__ inner  = dir ? d_cx : d_cy;
        const float* __restrict__ innern = dir ? d_nx : d_ny;
        const float* __restrict__ outer  = dir ? d_cy : d_cx;
        const float* __restrict__ outern = dir ? d_ny : d_nx;

        for (int j = tid; j < ilen; j += NTHR) {
            float a = -2.f * inner[(b * 3 + 0) * NN + i0 + j];
            float c = -2.f * inner[(b * 3 + 1) * NN + i0 + j];
            float e = -2.f * inner[(b * 3 + 2) * NN + i0 + j];
            float n = innern[b * NN + i0 + j];
            sIn[2 * j]     = make_float4(a, a, c, c);
            sIn[2 * j + 1] = make_float4(e, e, n, n);
        }
        __syncthreads();

        // pack the 4 outers into 2 f32x2 pairs
        u64 ox2[2], oy2[2], oz2[2];
        float xx[OPT], mn[OPT];
        #pragma unroll
        for (int p = 0; p < 2; p++) {
            int o0 = outer_base + tid + (2 * p) * NTHR;
            int o1 = o0 + NTHR;
            int c0 = (o0 < cnt) ? o0 : (cnt - 1);   // clamp; dropped at writeback
            int c1 = (o1 < cnt) ? o1 : (cnt - 1);
            ox2[p] = pack2(outer[(b * 3 + 0) * NN + c0], outer[(b * 3 + 0) * NN + c1]);
            oy2[p] = pack2(outer[(b * 3 + 1) * NN + c0], outer[(b * 3 + 1) * NN + c1]);
            oz2[p] = pack2(outer[(b * 3 + 2) * NN + c0], outer[(b * 3 + 2) * NN + c1]);
            xx[2 * p]     = outern[b * NN + c0];
            xx[2 * p + 1] = outern[b * NN + c1];
            mn[2 * p] = BIGV; mn[2 * p + 1] = BIGV;
        }

        #pragma unroll 4
        for (int j = 0; j < ilen; j++) {
            u64 ta, tc, te, tn;
            unsigned addr = sbase + (unsigned)j * 32u;
            asm volatile("ld.shared.v2.u64 {%0, %1}, [%2];"
                         : "=l"(ta), "=l"(tc) : "r"(addr));
            asm volatile("ld.shared.v2.u64 {%0, %1}, [%2];"
                         : "=l"(te), "=l"(tn) : "r"(addr + 16u));
            #pragma unroll
            for (int p = 0; p < 2; p++) {
                u64 d = fma2(ta, ox2[p], tn);      // |y|^2 - 2x.y (packed x2)
                d = fma2(tc, oy2[p], d);
                d = fma2(te, oz2[p], d);
                float lo, hi;
                unpack2(d, lo, hi);                 // register-pair rename
                mn[2 * p]     = fminf(mn[2 * p], lo);
                mn[2 * p + 1] = fminf(mn[2 * p + 1], hi);
            }
        }

        #pragma unroll
        for (int k = 0; k < OPT; k++) {
            int o = outer_base + tid + k * NTHR;
            if (o < cnt) {
                float v = fmaxf(mn[k] + xx[k], 0.f);   // >=0 so int-min == fp-min
                atomicMin((int*)&d_mins[(dir * BB + b) * NN + o],
                          __float_as_int(v));
            }
        }
    }
    grid_barrier();

    // ---------- Phase 3: per-(dir,b) masked sums. 256 units on bid<256 -----
    if (bid < 256) {
        const int db = bid >> 3;                 // dir*BB + b
        const int b = db & (BB - 1);
        const int chunk = bid & 7;
        const int cnt = d_cnt[b];
        const int base = chunk * 512 + tid * 2;

        float2 v = __ldcg((const float2*)&d_mins[db * NN + base]);
        float s = ((base < cnt) ? v.x : 0.f) + ((base + 1 < cnt) ? v.y : 0.f);
        #pragma unroll
        for (int off = 16; off; off >>= 1)
            s += __shfl_xor_sync(0xffffffffu, s, off);
        if ((tid & 31) == 0) sRed[tid >> 5] = s;
        __syncthreads();
        if (tid == 0) {
            float bs = 0.f;
            #pragma unroll
            for (int i = 0; i < NTHR / 32; i++) bs += sRed[i];
            atomicAdd(&d_sums[db], bs);
        }
    }
    grid_barrier();

    // ---------- Phase 4: parallel finalize ---------------------------------
    if (bid == 0 && tid < 32) {
        float v = __ldcg(&d_sums[tid]) / (float)__ldcg(&d_cnt[tid & (BB - 1)]);
        #pragma unroll
        for (int off = 16; off; off >>= 1)
            v += __shfl_xor_sync(0xffffffffu, v, off);
        if (tid == 0) out[0] = v / (float)BB;
    }
}

extern "C" void kernel_launch(void* const* d_in, const int* in_sizes, int n_in,
                              void* d_out, int out_size) {
    const float* x    = (const float*)d_in[0];
    const float* y    = (const float*)d_in[1];
    const int*   mask = (const int*)d_in[2];
    float* out = (float*)d_out;

    k_fused<<<NBLK, NTHR>>>(x, y, mask, out);
}

// round 14
// speedup vs baseline: 2.1456x; 1.0171x over previous
#include <cuda_runtime.h>

// GAEChamferLoss: B=16, C=3, N=4096, mask in {0,1}. Single fused persistent
// kernel: init -> compact -> pairwise-min -> reduce -> finalize, separated by
// software grid barriers (592 co-resident blocks, 4 per SM).
// d = |x|^2 + |y|^2 - 2 x.y; |y|^2 folded into the FMA chain, |x|^2 added
// after the min. Hot loop uses packed fma.rn.f32x2 (2 outers/instruction) with
// the inner tile pre-duplicated in smem so broadcasts need no pack movs.
// Phase 2 is a work-stealing queue over 4096 fine units for perfect balance.

#define BB 16
#define NN 4096
#define BIGV 1e10f

#define NBLK 592                   // 4 x 148 (all resident on 148- or 152-SM)
#define NTHR 256
#define IS 32                      // inner splits
#define OC 4                       // outer chunks of 1024 (covers cnt<=4096)
#define OPT 4                      // outers per thread (2 packed pairs)
#define OUTER_PER_BLOCK (NTHR * OPT)   // 1024
#define MAX_INNER ((NN + IS - 1) / IS) // 128 worst case
#define NUNITS (OC * 2 * IS * BB)      // 4096

typedef unsigned long long u64;

__device__ __forceinline__ u64 pack2(float lo, float hi) {
    u64 r; asm("mov.b64 %0, {%1, %2};" : "=l"(r) : "f"(lo), "f"(hi)); return r;
}
__device__ __forceinline__ u64 fma2(u64 a, u64 b, u64 c) {
    u64 d;
    asm("fma.rn.f32x2 %0, %1, %2, %3;" : "=l"(d) : "l"(a), "l"(b), "l"(c));
    return d;
}
__device__ __forceinline__ void unpack2(u64 v, float& lo, float& hi) {
    asm("mov.b64 {%0, %1}, %2;" : "=f"(lo), "=f"(hi) : "l"(v));
}

// Scratch (device globals — no allocations allowed)
__device__ float d_cx[BB * 3 * NN];
__device__ float d_cy[BB * 3 * NN];
__device__ float d_nx[BB * NN];
__device__ float d_ny[BB * NN];
__device__ int   d_cnt[BB];
__device__ __align__(16) float d_mins[2 * BB * NN];
__device__ float d_sums[2 * BB];
__device__ int   d_unit;                   // work-steal cursor
__device__ unsigned d_bar_arrive;          // static 0
__device__ volatile unsigned d_bar_gen;    // monotonically increasing

__device__ __forceinline__ void grid_barrier() {
    __syncthreads();
    __threadfence();
    if (threadIdx.x == 0) {
        unsigned gen = d_bar_gen;
        if (atomicAdd(&d_bar_arrive, 1u) == NBLK - 1) {
            atomicExch(&d_bar_arrive, 0u);
            __threadfence();
            d_bar_gen = gen + 1;
        } else {
            while (d_bar_gen == gen) { }
        }
    }
    __syncthreads();
}

__global__ __launch_bounds__(NTHR, 4)
void k_fused(const float* __restrict__ x, const float* __restrict__ y,
             const int* __restrict__ mask, float* __restrict__ out)
{
    const int tid = threadIdx.x;
    const int bid = blockIdx.x;
    // per inner point: two float4s = {-2a,-2a,-2c,-2c} and {-2e,-2e, n, n}
    __shared__ float4 sIn[2 * MAX_INNER];          // 4 KB
    __shared__ float sRed[NTHR / 32];
    __shared__ int sU;

    // ---------- Phase 0: init (cross-phase stores via .cg = L2 only) -------
    if (bid == 0) {
        if (tid < 2 * BB) __stcg(&d_sums[tid], 0.f);
        if (tid < BB) __stcg(&d_cnt[tid], 0);
        if (tid == 0) __stcg(&d_unit, 0);
    }
    {
        int idx = bid * NTHR + tid;                 // float2 slots: 65536 total
        if (idx < BB * NN)
            __stcg((float2*)&d_mins[idx * 2], make_float2(BIGV, BIGV));
    }
    grid_barrier();

    // ---------- Phase 1: warp-aggregated compaction + norms ----------------
    {
        const int g = bid * NTHR + tid;             // [b][i], 65536 total
        if (g < BB * NN) {
            const int b = g >> 12;
            const int i = g & (NN - 1);
            const int lane = tid & 31;
            const bool valid = mask[g] != 0;
            const unsigned bal = __ballot_sync(0xffffffffu, valid);
            int base = 0;
            if (lane == 0 && bal) base = atomicAdd(&d_cnt[b], __popc(bal));
            base = __shfl_sync(0xffffffffu, base, 0);
            if (valid) {
                const int slot = base + __popc(bal & ((1u << lane) - 1u));
                float x0 = x[(b * 3 + 0) * NN + i];
                float x1 = x[(b * 3 + 1) * NN + i];
                float x2 = x[(b * 3 + 2) * NN + i];
                float y0 = y[(b * 3 + 0) * NN + i];
                float y1 = y[(b * 3 + 1) * NN + i];
                float y2 = y[(b * 3 + 2) * NN + i];
                __stcg(&d_cx[(b * 3 + 0) * NN + slot], x0);
                __stcg(&d_cx[(b * 3 + 1) * NN + slot], x1);
                __stcg(&d_cx[(b * 3 + 2) * NN + slot], x2);
                __stcg(&d_cy[(b * 3 + 0) * NN + slot], y0);
                __stcg(&d_cy[(b * 3 + 1) * NN + slot], y1);
                __stcg(&d_cy[(b * 3 + 2) * NN + slot], y2);
                __stcg(&d_nx[b * NN + slot], fmaf(x2, x2, fmaf(x1, x1, x0 * x0)));
                __stcg(&d_ny[b * NN + slot], fmaf(y2, y2, fmaf(y1, y1, y0 * y0)));
            }
        }
    }
    grid_barrier();

    // ---------- Phase 2: pairwise mins, work-stealing over 4096 units ------
    // unit u (oc slowest => heavy units pulled first, empties drain cheap):
    //   b = u&15, isplit = (u>>4)&31, dir = (u>>9)&1, oc = u>>10
    const unsigned sbase = (unsigned)__cvta_generic_to_shared(sIn);
    for (;;) {
        __syncthreads();                   // protects sIn reuse + sU
        if (tid == 0) sU = atomicAdd(&d_unit, 1);
        __syncthreads();
        const int u = sU;
        if (u >= NUNITS) break;

        const int b = u & 15;
        const int isplit = (u >> 4) & 31;
        const int dir = (u >> 9) & 1;
        const int oc = u >> 10;
        const int cnt = d_cnt[b];
        const int outer_base = oc * OUTER_PER_BLOCK;
        if (outer_base >= cnt) continue;

        const int chunk = (cnt + IS - 1) / IS;
        const int i0 = isplit * chunk;
        const int ilen = min(cnt, i0 + chunk) - i0;
        if (ilen <= 0) continue;

        const float* __restrict__ inner  = dir ? d_cx : d_cy;
        const float* __restrict__ innern = dir ? d_nx : d_ny;
        const float* __restrict__ outer  = dir ? d_cy : d_cx;
        const float* __restrict__ outern = dir ? d_ny : d_nx;

        if (tid < ilen) {                  // ilen <= 128 < NTHR
            int j = tid;
            float a = -2.f * inner[(b * 3 + 0) * NN + i0 + j];
            float c = -2.f * inner[(b * 3 + 1) * NN + i0 + j];
            float e = -2.f * inner[(b * 3 + 2) * NN + i0 + j];
            float n = innern[b * NN + i0 + j];
            sIn[2 * j]     = make_float4(a, a, c, c);
            sIn[2 * j + 1] = make_float4(e, e, n, n);
        }
        __syncthreads();

        // pack the 4 outers into 2 f32x2 pairs
        u64 ox2[2], oy2[2], oz2[2];
        float xx[OPT], mn[OPT];
        #pragma unroll
        for (int p = 0; p < 2; p++) {
            int o0 = outer_base + tid + (2 * p) * NTHR;
            int o1 = o0 + NTHR;
            int c0 = (o0 < cnt) ? o0 : (cnt - 1);   // clamp; dropped at writeback
            int c1 = (o1 < cnt) ? o1 : (cnt - 1);
            ox2[p] = pack2(outer[(b * 3 + 0) * NN + c0], outer[(b * 3 + 0) * NN + c1]);
            oy2[p] = pack2(outer[(b * 3 + 1) * NN + c0], outer[(b * 3 + 1) * NN + c1]);
            oz2[p] = pack2(outer[(b * 3 + 2) * NN + c0], outer[(b * 3 + 2) * NN + c1]);
            xx[2 * p]     = outern[b * NN + c0];
            xx[2 * p + 1] = outern[b * NN + c1];
            mn[2 * p] = BIGV; mn[2 * p + 1] = BIGV;
        }

        #pragma unroll 4
        for (int j = 0; j < ilen; j++) {
            u64 ta, tc, te, tn;
            unsigned addr = sbase + (unsigned)j * 32u;
            asm volatile("ld.shared.v2.u64 {%0, %1}, [%2];"
                         : "=l"(ta), "=l"(tc) : "r"(addr));
            asm volatile("ld.shared.v2.u64 {%0, %1}, [%2];"
                         : "=l"(te), "=l"(tn) : "r"(addr + 16u));
            #pragma unroll
            for (int p = 0; p < 2; p++) {
                u64 d = fma2(ta, ox2[p], tn);      // |y|^2 - 2x.y (packed x2)
                d = fma2(tc, oy2[p], d);
                d = fma2(te, oz2[p], d);
                float lo, hi;
                unpack2(d, lo, hi);                 // register-pair rename
                mn[2 * p]     = fminf(mn[2 * p], lo);
                mn[2 * p + 1] = fminf(mn[2 * p + 1], hi);
            }
        }

        #pragma unroll
        for (int k = 0; k < OPT; k++) {
            int o = outer_base + tid + k * NTHR;
            if (o < cnt) {
                float v = fmaxf(mn[k] + xx[k], 0.f);   // >=0 so int-min == fp-min
                atomicMin((int*)&d_mins[(dir * BB + b) * NN + o],
                          __float_as_int(v));
            }
        }
    }
    grid_barrier();

    // ---------- Phase 3: per-(dir,b) masked sums. 256 units on bid<256 -----
    if (bid < 256) {
        const int db = bid >> 3;                 // dir*BB + b
        const int b = db & (BB - 1);
        const int chunk = bid & 7;
        const int cnt = d_cnt[b];
        const int base = chunk * 512 + tid * 2;

        float2 v = __ldcg((const float2*)&d_mins[db * NN + base]);
        float s = ((base < cnt) ? v.x : 0.f) + ((base + 1 < cnt) ? v.y : 0.f);
        #pragma unroll
        for (int off = 16; off; off >>= 1)
            s += __shfl_xor_sync(0xffffffffu, s, off);
        if ((tid & 31) == 0) sRed[tid >> 5] = s;
        __syncthreads();
        if (tid == 0) {
            float bs = 0.f;
            #pragma unroll
            for (int i = 0; i < NTHR / 32; i++) bs += sRed[i];
            atomicAdd(&d_sums[db], bs);
        }
    }
    grid_barrier();

    // ---------- Phase 4: parallel finalize ---------------------------------
    if (bid == 0 && tid < 32) {
        float v = __ldcg(&d_sums[tid]) / (float)__ldcg(&d_cnt[tid & (BB - 1)]);
        #pragma unroll
        for (int off = 16; off; off >>= 1)
            v += __shfl_xor_sync(0xffffffffu, v, off);
        if (tid == 0) out[0] = v / (float)BB;
    }
}

extern "C" void kernel_launch(void* const* d_in, const int* in_sizes, int n_in,
                              void* d_out, int out_size) {
    const float* x    = (const float*)d_in[0];
    const float* y    = (const float*)d_in[1];
    const int*   mask = (const int*)d_in[2];
    float* out = (float*)d_out;

    k_fused<<<NBLK, NTHR>>>(x, y, mask, out);
}